// round 5
// baseline (speedup 1.0000x reference)
#include <cuda_runtime.h>
#include <math.h>
#include <stdint.h>

#define HH    64
#define DIMC  512     // per-axis sinusoid width
#define ODIM  256     // output dim
#define BATCH 8
#define TILE_BYTES (HH * ODIM * 4)   // 65536: one (h,b) output tile

// C[r][o]: r<64 -> A[h][o] (W cols 0:512), r>=64 -> B[w][o] (W cols 512:1024)
// Static-zero at load; k2's epilogue re-zeroes it, so every launch sees C==0.
__device__ float        g_C[2 * HH][ODIM];
__device__ unsigned int g_end_cnt;    // k2 exit tickets (reset by last block)

// ---------------------------------------------------------------------------
// k1: fused embed + split-K GEMM (unchanged from R4 — not the bottleneck).
//   C[half*64+m][o] += sum_{k in chunk} embed(m)[k] * W[o][half*512 + k]
// grid (16 k-chunks, 4 n-tiles, 2 halves) = 128 blocks x 256 threads.
// ---------------------------------------------------------------------------
__global__ __launch_bounds__(256) void k1_embed_gemm(const float* __restrict__ W) {
    const int k0   = blockIdx.x * 32;
    const int n0   = blockIdx.y * 64;
    const int half = blockIdx.z;
    const int off  = half * DIMC;

    __shared__ float fr[32];
    __shared__ float Es[64][36];
    __shared__ float Ws[32][68];

    const int t = threadIdx.x;

    if (t < 32) {
        int c = k0 + t;
        float expo = (c < 256) ? (float)(2 * c + 1) * (1.0f / 512.0f)
                               : (float)(2 * (c - 256)) * (1.0f / 512.0f);
        fr[t] = expf(-expo * 6.907755278982137f);   // 1000^(-expo)
    }
    __syncthreads();

    #pragma unroll
    for (int e = t; e < 64 * 32; e += 256) {
        int kk = e & 31, m = e >> 5;
        float zf = (float)m * fr[kk];
        Es[m][kk] = (k0 + kk < 256) ? sinf(zf) : cosf(zf);
    }
    #pragma unroll
    for (int e = t; e < 64 * 32; e += 256) {
        int kk = e & 31, i = e >> 5;
        Ws[kk][i] = W[(size_t)(n0 + i) * (2 * DIMC) + off + k0 + kk];
    }
    __syncthreads();

    const int tx = t & 15, ty = t >> 4;
    const int mb = ty * 4, nb = tx * 4;

    float acc[4][4] = {};
    #pragma unroll 8
    for (int k = 0; k < 32; k++) {
        float4 b = *(const float4*)&Ws[k][nb];
        float a0 = Es[mb + 0][k];
        float a1 = Es[mb + 1][k];
        float a2 = Es[mb + 2][k];
        float a3 = Es[mb + 3][k];
        acc[0][0] += a0 * b.x; acc[0][1] += a0 * b.y; acc[0][2] += a0 * b.z; acc[0][3] += a0 * b.w;
        acc[1][0] += a1 * b.x; acc[1][1] += a1 * b.y; acc[1][2] += a1 * b.z; acc[1][3] += a1 * b.w;
        acc[2][0] += a2 * b.x; acc[2][1] += a2 * b.y; acc[2][2] += a2 * b.z; acc[2][3] += a2 * b.w;
        acc[3][0] += a3 * b.x; acc[3][1] += a3 * b.y; acc[3][2] += a3 * b.z; acc[3][3] += a3 * b.w;
    }

    const int rbase = half * 64 + mb;
    #pragma unroll
    for (int i = 0; i < 4; i++)
        #pragma unroll
        for (int j = 0; j < 4; j++)
            atomicAdd(&g_C[rbase + i][n0 + nb + j], acc[i][j]);
}

// ---------------------------------------------------------------------------
// k2: TMA bulk-store version.
// Block (h, b): build tile[w][o] = C[h][o] + C[64+w][o] in smem (64 KB),
// then a single cp.async.bulk moves it to out[b][h][*][*] (contiguous 64 KB).
// Removes ~2M STG.128 issue slots — store path rides TMA to the LTS cap.
// ---------------------------------------------------------------------------
__global__ __launch_bounds__(256) void k2_write_tma(float* __restrict__ out) {
    __shared__ __align__(128) float tile[HH][ODIM];   // 64 KB
    __shared__ unsigned int ticket;

    const int t = threadIdx.x;
    const int h = blockIdx.x;      // 0..63
    const int b = blockIdx.y;      // 0..7

    const int q  = t & 63;         // float4 column index (o/4)
    const int wg = t >> 6;         // 0..3 -> rows wg*16 .. wg*16+15

    float4 a = *(const float4*)&g_C[h][q * 4];
    #pragma unroll
    for (int i = 0; i < 16; i++) {
        int w = wg * 16 + i;
        float4 bb = *(const float4*)&g_C[64 + w][q * 4];
        float4 v;
        v.x = a.x + bb.x; v.y = a.y + bb.y; v.z = a.z + bb.z; v.w = a.w + bb.w;
        *(float4*)&tile[w][q * 4] = v;
    }
    __syncthreads();               // tile complete; all g_C reads in block done

    if (t == 0) {
        // make generic-proxy STS visible to the async (TMA) proxy
        asm volatile("fence.proxy.async.shared::cta;" ::: "memory");
        uint32_t saddr;
        asm("{ .reg .u64 tmp; cvta.to.shared.u64 tmp, %1; cvt.u32.u64 %0, tmp; }"
            : "=r"(saddr) : "l"((const void*)tile));
        const float* dst = out + ((size_t)b * (HH * HH) + (size_t)h * HH) * ODIM;
        asm volatile("cp.async.bulk.global.shared::cta.bulk_group [%0], [%1], %2;"
                     :: "l"(dst), "r"(saddr), "n"(TILE_BYTES) : "memory");
        asm volatile("cp.async.bulk.commit_group;" ::: "memory");
        ticket = atomicAdd(&g_end_cnt, 1u);
    }
    __syncthreads();

    // Last-arriving block zeroes g_C for the next replay. All 512 blocks have
    // ticketed -> all g_C reads are complete. TMA writes touch only out/smem.
    if (ticket == (unsigned)(HH * BATCH - 1)) {
        float4 z4 = make_float4(0.f, 0.f, 0.f, 0.f);
        float4* cp = (float4*)g_C;
        #pragma unroll
        for (int i = t; i < (2 * HH * ODIM) / 4; i += 256)
            cp[i] = z4;
        if (t == 0) g_end_cnt = 0;   // ordered vs next launch by kernel boundary
    }

    if (t == 0) {
        asm volatile("cp.async.bulk.wait_group 0;" ::: "memory");
    }
}

// ---------------------------------------------------------------------------
extern "C" void kernel_launch(void* const* d_in, const int* in_sizes, int n_in,
                              void* d_out, int out_size) {
    const float* W = (const float*)d_in[0];   // W_im: (256, 1024) fp32
    float* out = (float*)d_out;               // (8, 64, 64, 256, 1) fp32

    dim3 g1(16, 4, 2);
    k1_embed_gemm<<<g1, 256>>>(W);
    dim3 g2(HH, BATCH);
    k2_write_tma<<<g2, 256>>>(out);
}

// round 6
// speedup vs baseline: 1.1212x; 1.1212x over previous
#include <cuda_runtime.h>
#include <math.h>
#include <stdint.h>

#define HH    64
#define DIMC  512     // per-axis sinusoid width
#define ODIM  256     // output dim
#define BATCH 8

#define SUB_ROWS   16                         // w-rows per subtile
#define SUB_BYTES  (SUB_ROWS * ODIM * 4)      // 16384
#define NSUB       (HH / SUB_ROWS)            // 4 subtiles per (h,b) tile

// C[r][o]: r<64 -> A[h][o] (W cols 0:512), r>=64 -> B[w][o] (W cols 512:1024)
// Static-zero at load; k2's epilogue re-zeroes it, so every launch sees C==0.
__device__ float        g_C[2 * HH][ODIM];
__device__ unsigned int g_end_cnt;    // k2 exit tickets (reset by last block)

// ---------------------------------------------------------------------------
// k1: fused embed + split-K GEMM, fast-math transcendentals.
//   C[half*64+m][o] += sum_{k in chunk} embed(m)[k] * W[o][half*512 + k]
// grid (16 k-chunks, 4 n-tiles, 2 halves) = 128 blocks x 256 threads.
// ---------------------------------------------------------------------------
__global__ __launch_bounds__(256) void k1_embed_gemm(const float* __restrict__ W) {
    const int k0   = blockIdx.x * 32;
    const int n0   = blockIdx.y * 64;
    const int half = blockIdx.z;
    const int off  = half * DIMC;

    __shared__ float fr[32];
    __shared__ float Es[64][36];
    __shared__ float Ws[32][68];

    const int t = threadIdx.x;

    if (t < 32) {
        int c = k0 + t;
        float expo = (c < 256) ? (float)(2 * c + 1) * (1.0f / 512.0f)
                               : (float)(2 * (c - 256)) * (1.0f / 512.0f);
        fr[t] = __expf(-expo * 6.907755278982137f);   // 1000^(-expo)
    }
    __syncthreads();

    #pragma unroll
    for (int e = t; e < 64 * 32; e += 256) {
        int kk = e & 31, m = e >> 5;
        float zf = (float)m * fr[kk];
        Es[m][kk] = (k0 + kk < 256) ? __sinf(zf) : __cosf(zf);
    }
    #pragma unroll
    for (int e = t; e < 64 * 32; e += 256) {
        int kk = e & 31, i = e >> 5;
        Ws[kk][i] = W[(size_t)(n0 + i) * (2 * DIMC) + off + k0 + kk];
    }
    __syncthreads();

    const int tx = t & 15, ty = t >> 4;
    const int mb = ty * 4, nb = tx * 4;

    float acc[4][4] = {};
    #pragma unroll 8
    for (int k = 0; k < 32; k++) {
        float4 b = *(const float4*)&Ws[k][nb];
        float a0 = Es[mb + 0][k];
        float a1 = Es[mb + 1][k];
        float a2 = Es[mb + 2][k];
        float a3 = Es[mb + 3][k];
        acc[0][0] += a0 * b.x; acc[0][1] += a0 * b.y; acc[0][2] += a0 * b.z; acc[0][3] += a0 * b.w;
        acc[1][0] += a1 * b.x; acc[1][1] += a1 * b.y; acc[1][2] += a1 * b.z; acc[1][3] += a1 * b.w;
        acc[2][0] += a2 * b.x; acc[2][1] += a2 * b.y; acc[2][2] += a2 * b.z; acc[2][3] += a2 * b.w;
        acc[3][0] += a3 * b.x; acc[3][1] += a3 * b.y; acc[3][2] += a3 * b.z; acc[3][3] += a3 * b.w;
    }

    const int rbase = half * 64 + mb;
    #pragma unroll
    for (int i = 0; i < 4; i++)
        #pragma unroll
        for (int j = 0; j < 4; j++)
            atomicAdd(&g_C[rbase + i][n0 + nb + j], acc[i][j]);
}

// ---------------------------------------------------------------------------
// k2: double-buffered TMA bulk store.
// Block (h, b): 4 subtiles of 16 w-rows; build subtile in smem buf[s&1],
// bulk-store 16 KB, pipeline with commit_group / wait_group<=1.
// grid (64, 8) = 512 blocks x 256 threads, 32 KB smem -> ~7 CTAs/SM.
// ---------------------------------------------------------------------------
__global__ __launch_bounds__(256) void k2_write_tma(float* __restrict__ out) {
    __shared__ __align__(128) float buf[2][SUB_ROWS][ODIM];   // 2 x 16 KB
    __shared__ unsigned int ticket;

    const int t = threadIdx.x;
    const int h = blockIdx.x;      // 0..63
    const int b = blockIdx.y;      // 0..7

    const int q  = t & 63;         // float4 column index (o/4)
    const int rg = t >> 6;         // 0..3 -> rows rg*4 .. rg*4+3 within subtile

    uint32_t sbase[2];
    asm("{ .reg .u64 tmp; cvta.to.shared.u64 tmp, %1; cvt.u32.u64 %0, tmp; }"
        : "=r"(sbase[0]) : "l"((const void*)buf[0]));
    sbase[1] = sbase[0] + SUB_BYTES;

    float4 a = *(const float4*)&g_C[h][q * 4];   // row h, reused by all subtiles
    float* dst = out + ((size_t)b * (HH * HH) + (size_t)h * HH) * ODIM;

    #pragma unroll
    for (int s = 0; s < NSUB; s++) {
        const int bi = s & 1;
        if (s >= 2) {
            // recycle buf[bi]: its TMA (group s-2) must be done; allow 1 in flight
            if (t == 0)
                asm volatile("cp.async.bulk.wait_group 1;" ::: "memory");
            __syncthreads();
        }
        // build 16 rows: thread covers rows rg*4..rg*4+3, col q
        #pragma unroll
        for (int i = 0; i < 4; i++) {
            int wr = rg * 4 + i;                       // row within subtile
            int w  = s * SUB_ROWS + wr;                // global w
            float4 bb = *(const float4*)&g_C[64 + w][q * 4];
            float4 v;
            v.x = a.x + bb.x; v.y = a.y + bb.y; v.z = a.z + bb.z; v.w = a.w + bb.w;
            *(float4*)&buf[bi][wr][q * 4] = v;
        }
        __syncthreads();
        if (t == 0) {
            asm volatile("fence.proxy.async.shared::cta;" ::: "memory");
            asm volatile("cp.async.bulk.global.shared::cta.bulk_group [%0], [%1], %2;"
                         :: "l"(dst + (size_t)s * SUB_ROWS * ODIM),
                            "r"(sbase[bi]), "n"(SUB_BYTES) : "memory");
            asm volatile("cp.async.bulk.commit_group;" ::: "memory");
        }
        // no sync needed: next iteration writes the OTHER buffer
    }

    // ---- epilogue: all g_C reads for this block completed at last build-sync
    __syncthreads();
    if (t == 0) ticket = atomicAdd(&g_end_cnt, 1u);
    __syncthreads();

    if (ticket == (unsigned)(HH * BATCH - 1)) {
        // every block has finished reading g_C -> safe to zero for next replay
        float4 z4 = make_float4(0.f, 0.f, 0.f, 0.f);
        float4* cp = (float4*)g_C;
        #pragma unroll
        for (int i = t; i < (2 * HH * ODIM) / 4; i += 256)
            cp[i] = z4;
        if (t == 0) g_end_cnt = 0;   // ordered vs next launch by kernel boundary
    }

    // hold smem alive until all bulk stores drained (t0 exits last)
    if (t == 0)
        asm volatile("cp.async.bulk.wait_group 0;" ::: "memory");
}

// ---------------------------------------------------------------------------
extern "C" void kernel_launch(void* const* d_in, const int* in_sizes, int n_in,
                              void* d_out, int out_size) {
    const float* W = (const float*)d_in[0];   // W_im: (256, 1024) fp32
    float* out = (float*)d_out;               // (8, 64, 64, 256, 1) fp32

    dim3 g1(16, 4, 2);
    k1_embed_gemm<<<g1, 256>>>(W);
    dim3 g2(HH, BATCH);
    k2_write_tma<<<g2, 256>>>(out);
}

// round 7
// speedup vs baseline: 1.2596x; 1.1234x over previous
#include <cuda_runtime.h>
#include <math.h>
#include <stdint.h>

#define HH    64
#define DIMC  512     // per-axis sinusoid width
#define ODIM  256     // output dim
#define BATCH 8
#define NSPLIT 16     // split-K partials

// Partial sums: g_Cpart[kc][r][o]; r<64 -> A-half (W cols 0:512), r>=64 -> B-half.
// Plain overwrite stores every launch -> no zeroing, no atomics, no state.
__device__ float g_Cpart[NSPLIT][2 * HH][ODIM];   // 2 MB
__device__ float g_C[2 * HH][ODIM];               // reduced result (128 KB)

// ---------------------------------------------------------------------------
// k1: fused embed + split-K GEMM partials (plain stores).
//   Cpart[kc][half*64+m][o] = sum_{k in chunk kc} embed(m)[k] * W[o][half*512+k]
// grid (16 kc, 4 ntiles, 2 halves) = 128 blocks x 256 threads.
// ---------------------------------------------------------------------------
__global__ __launch_bounds__(256) void k1_embed_gemm(const float* __restrict__ W) {
    const int kc   = blockIdx.x;
    const int k0   = kc * 32;
    const int n0   = blockIdx.y * 64;
    const int half = blockIdx.z;
    const int off  = half * DIMC;

    __shared__ float fr[32];
    __shared__ float Es[64][36];
    __shared__ float Ws[32][68];

    const int t = threadIdx.x;

    if (t < 32) {
        int c = k0 + t;
        float expo = (c < 256) ? (float)(2 * c + 1) * (1.0f / 512.0f)
                               : (float)(2 * (c - 256)) * (1.0f / 512.0f);
        fr[t] = __expf(-expo * 6.907755278982137f);   // 1000^(-expo)
    }
    __syncthreads();

    #pragma unroll
    for (int e = t; e < 64 * 32; e += 256) {
        int kk = e & 31, m = e >> 5;
        float zf = (float)m * fr[kk];
        Es[m][kk] = (k0 + kk < 256) ? __sinf(zf) : __cosf(zf);
    }
    #pragma unroll
    for (int e = t; e < 64 * 32; e += 256) {
        int kk = e & 31, i = e >> 5;
        Ws[kk][i] = W[(size_t)(n0 + i) * (2 * DIMC) + off + k0 + kk];
    }
    __syncthreads();

    const int tx = t & 15, ty = t >> 4;
    const int mb = ty * 4, nb = tx * 4;

    float acc[4][4] = {};
    #pragma unroll 8
    for (int k = 0; k < 32; k++) {
        float4 b = *(const float4*)&Ws[k][nb];
        float a0 = Es[mb + 0][k];
        float a1 = Es[mb + 1][k];
        float a2 = Es[mb + 2][k];
        float a3 = Es[mb + 3][k];
        acc[0][0] += a0 * b.x; acc[0][1] += a0 * b.y; acc[0][2] += a0 * b.z; acc[0][3] += a0 * b.w;
        acc[1][0] += a1 * b.x; acc[1][1] += a1 * b.y; acc[1][2] += a1 * b.z; acc[1][3] += a1 * b.w;
        acc[2][0] += a2 * b.x; acc[2][1] += a2 * b.y; acc[2][2] += a2 * b.z; acc[2][3] += a2 * b.w;
        acc[3][0] += a3 * b.x; acc[3][1] += a3 * b.y; acc[3][2] += a3 * b.z; acc[3][3] += a3 * b.w;
    }

    const int rbase = half * 64 + mb;
    #pragma unroll
    for (int i = 0; i < 4; i++) {
        float4 v = make_float4(acc[i][0], acc[i][1], acc[i][2], acc[i][3]);
        *(float4*)&g_Cpart[kc][rbase + i][n0 + nb] = v;
    }
}

// ---------------------------------------------------------------------------
// k1b: reduce 16 partials -> g_C. 8192 float4 elements, 64 blocks x 128 thr.
// Coalesced LDG.128, MLP=16, plain stores. Stateless.
// ---------------------------------------------------------------------------
__global__ __launch_bounds__(128) void k1b_reduce() {
    const int idx = blockIdx.x * 128 + threadIdx.x;     // 0..8191 float4 slots
    const float4* p = (const float4*)g_Cpart;
    const int stride = (2 * HH * ODIM) / 4;             // 8192 float4 per partial

    float4 s = p[idx];
    #pragma unroll
    for (int k = 1; k < NSPLIT; k++) {
        float4 v = p[idx + k * stride];
        s.x += v.x; s.y += v.y; s.z += v.z; s.w += v.w;
    }
    ((float4*)g_C)[idx] = s;
}

// ---------------------------------------------------------------------------
// k2: broadcast write, read-amortized.
//   out[b][h][w][o] = C[h][o] + C[64+w][o]
// block (h, wg, bg): h fixed, w in [wg*8, wg*8+8), b in [bg*4, bg*4+4).
// Reads 9 KB of C per block (was 65 KB) -> L2 read traffic 33.5 -> 9.2 MB.
// grid (64, 8, 2) = 1024 blocks x 256 threads; 8 coalesced STG.128 per thread.
// ---------------------------------------------------------------------------
__global__ __launch_bounds__(256) void k2_write(float* __restrict__ out) {
    const int t  = threadIdx.x;
    const int q  = t & 63;        // float4 column (o = 4q)
    const int rg = t >> 6;        // 0..3
    const int h  = blockIdx.x;    // 0..63
    const int wg = blockIdx.y;    // 0..7
    const int bg = blockIdx.z;    // 0..1

    const int w0 = wg * 8 + rg * 2;
    const int w1 = w0 + 1;

    float4 a  = *(const float4*)&g_C[h][q * 4];
    float4 e0 = *(const float4*)&g_C[64 + w0][q * 4];
    float4 e1 = *(const float4*)&g_C[64 + w1][q * 4];

    float4 v0, v1;
    v0.x = a.x + e0.x; v0.y = a.y + e0.y; v0.z = a.z + e0.z; v0.w = a.w + e0.w;
    v1.x = a.x + e1.x; v1.y = a.y + e1.y; v1.z = a.z + e1.z; v1.w = a.w + e1.w;

    const size_t colo = (size_t)q * 4;
    #pragma unroll
    for (int j = 0; j < 4; j++) {
        int b = bg * 4 + j;
        size_t base = (((size_t)b * HH + h) * HH) * ODIM + colo;
        *(float4*)&out[base + (size_t)w0 * ODIM] = v0;
        *(float4*)&out[base + (size_t)w1 * ODIM] = v1;
    }
}

// ---------------------------------------------------------------------------
extern "C" void kernel_launch(void* const* d_in, const int* in_sizes, int n_in,
                              void* d_out, int out_size) {
    const float* W = (const float*)d_in[0];   // W_im: (256, 1024) fp32
    float* out = (float*)d_out;               // (8, 64, 64, 256, 1) fp32

    dim3 g1(NSPLIT, 4, 2);
    k1_embed_gemm<<<g1, 256>>>(W);
    k1b_reduce<<<64, 128>>>();
    dim3 g2(HH, 8, 2);
    k2_write<<<g2, 256>>>(out);
}